// round 5
// baseline (speedup 1.0000x reference)
#include <cuda_runtime.h>

#define B_ 4
#define C_ 64
#define N_ 4096

// Scratch (static __device__ arrays per allocation rules)
__device__ float g_q[B_ * C_ * N_]; // [b][c][n]
__device__ float g_k[B_ * C_ * N_]; // [b][c][n]
__device__ float g_v[B_ * N_ * C_]; // [b][n][c]
__device__ float g_o[B_ * N_ * C_]; // [b][n][c]

// ---------------------------------------------------------------------------
// QKV: qkv[o,n] = sum_c w[o,c] * x[b,c,n] + bias[o]
// grid (N/64, 3, B), 256 thr. og=0->q, 1->k (stored [b][c][n]); og=2->v ([b][n][c])
// ---------------------------------------------------------------------------
__global__ __launch_bounds__(256) void qkv_kernel(
    const float* __restrict__ x, const float* __restrict__ w,
    const float* __restrict__ bias)
{
    const int b  = blockIdx.z;
    const int og = blockIdx.y;
    const int n0 = blockIdx.x * 64;

    __shared__ float xs[64 * 64];   // [c][n] pitch 64
    __shared__ float ws[64 * 65];   // [o][c] pitch 65

    const int t  = threadIdx.x;
    const int tx = t & 15;
    const int ty = t >> 4;

    #pragma unroll
    for (int it = 0; it < 4; ++it) {
        int idx = it * 256 + t;
        int r = idx >> 4, cg = (idx & 15) << 2;
        float4 xv = *(const float4*)&x[(b * C_ + r) * N_ + n0 + cg];
        *(float4*)&xs[r * 64 + cg] = xv;
        float4 wv = *(const float4*)&w[(og * 64 + r) * C_ + cg];
        ws[r * 65 + cg + 0] = wv.x;
        ws[r * 65 + cg + 1] = wv.y;
        ws[r * 65 + cg + 2] = wv.z;
        ws[r * 65 + cg + 3] = wv.w;
    }
    __syncthreads();

    float acc[4][4] = {};
    #pragma unroll 8
    for (int c = 0; c < 64; ++c) {
        float4 x4 = *(float4*)&xs[c * 64 + tx * 4];
        float xv[4] = {x4.x, x4.y, x4.z, x4.w};
        float wr[4];
        #pragma unroll
        for (int i = 0; i < 4; ++i) wr[i] = ws[(ty * 4 + i) * 65 + c];
        #pragma unroll
        for (int i = 0; i < 4; ++i)
            #pragma unroll
            for (int j = 0; j < 4; ++j)
                acc[i][j] += wr[i] * xv[j];
    }

    if (og < 2) {
        float* dst = (og == 0) ? g_q : g_k;
        #pragma unroll
        for (int i = 0; i < 4; ++i) {
            int o = ty * 4 + i;
            float bb = bias[og * 64 + o];
            float4 r4 = make_float4(acc[i][0] + bb, acc[i][1] + bb,
                                    acc[i][2] + bb, acc[i][3] + bb);
            *(float4*)&dst[(b * C_ + o) * N_ + n0 + tx * 4] = r4;
        }
    } else {
        #pragma unroll
        for (int i = 0; i < 4; ++i) {
            int o = ty * 4 + i;
            float bb = bias[2 * 64 + o];
            #pragma unroll
            for (int j = 0; j < 4; ++j) {
                int n = n0 + tx * 4 + j;
                g_v[(b * N_ + n) * C_ + o] = acc[i][j] + bb;
            }
        }
    }
}

// ---------------------------------------------------------------------------
// Flash attention: grid (N/64, B), 256 thr, dynamic smem.
// S[r,m] = sum_c Q[c,r]K[c,m] * 0.125 ; online softmax; O[r,c] += P[r,m]V[m,c]
// ---------------------------------------------------------------------------
#define ATTN_SMEM ((3 * 64 * 64 + 64 * 65) * 4)

__global__ __launch_bounds__(256) void attn_kernel()
{
    extern __shared__ float sm[];
    float* Qs = sm;                 // [c][r] 64x64
    float* Ks = sm + 64 * 64;       // [c][m] 64x64
    float* Vs = sm + 2 * 64 * 64;   // [m][c] 64x64
    float* Ps = sm + 3 * 64 * 64;   // [r][m] pitch 65

    const int b  = blockIdx.y;
    const int q0 = blockIdx.x * 64;
    const int t  = threadIdx.x;
    const int tx = t & 15;
    const int ty = t >> 4;

    #pragma unroll
    for (int it = 0; it < 4; ++it) {
        int idx = it * 256 + t;
        int r = idx >> 4, cg = (idx & 15) << 2;
        *(float4*)&Qs[r * 64 + cg] =
            *(const float4*)&g_q[(b * C_ + r) * N_ + q0 + cg];
    }

    float m_i[4], l_i[4], o_i[4][4];
    #pragma unroll
    for (int i = 0; i < 4; ++i) {
        m_i[i] = -1e30f;
        l_i[i] = 0.f;
        #pragma unroll
        for (int j = 0; j < 4; ++j) o_i[i][j] = 0.f;
    }

    for (int k0 = 0; k0 < N_; k0 += 64) {
        __syncthreads();  // Q-load done (iter 0) / prior PV readers done
        #pragma unroll
        for (int it = 0; it < 4; ++it) {
            int idx = it * 256 + t;
            int r = idx >> 4, cg = (idx & 15) << 2;
            *(float4*)&Ks[r * 64 + cg] =
                *(const float4*)&g_k[(b * C_ + r) * N_ + k0 + cg];
            *(float4*)&Vs[r * 64 + cg] =
                *(const float4*)&g_v[(b * N_ + k0 + r) * C_ + cg];
        }
        __syncthreads();

        // ---- S = Q^T K ----
        float s[4][4] = {};
        #pragma unroll 8
        for (int c = 0; c < 64; ++c) {
            float4 q4 = *(float4*)&Qs[c * 64 + ty * 4];
            float4 k4 = *(float4*)&Ks[c * 64 + tx * 4];
            float qv[4] = {q4.x, q4.y, q4.z, q4.w};
            float kv[4] = {k4.x, k4.y, k4.z, k4.w};
            #pragma unroll
            for (int i = 0; i < 4; ++i)
                #pragma unroll
                for (int j = 0; j < 4; ++j)
                    s[i][j] += qv[i] * kv[j];
        }

        // ---- online softmax ----
        #pragma unroll
        for (int i = 0; i < 4; ++i) {
            #pragma unroll
            for (int j = 0; j < 4; ++j) s[i][j] *= 0.125f;
            float mx = fmaxf(fmaxf(s[i][0], s[i][1]), fmaxf(s[i][2], s[i][3]));
            mx = fmaxf(mx, __shfl_xor_sync(0xffffffffu, mx, 1));
            mx = fmaxf(mx, __shfl_xor_sync(0xffffffffu, mx, 2));
            mx = fmaxf(mx, __shfl_xor_sync(0xffffffffu, mx, 4));
            mx = fmaxf(mx, __shfl_xor_sync(0xffffffffu, mx, 8));
            float mnew = fmaxf(m_i[i], mx);
            float corr = __expf(m_i[i] - mnew);
            m_i[i] = mnew;
            l_i[i] *= corr;
            #pragma unroll
            for (int j = 0; j < 4; ++j) o_i[i][j] *= corr;
            float rs = 0.f;
            #pragma unroll
            for (int j = 0; j < 4; ++j) {
                s[i][j] = __expf(s[i][j] - mnew);
                rs += s[i][j];
            }
            rs += __shfl_xor_sync(0xffffffffu, rs, 1);
            rs += __shfl_xor_sync(0xffffffffu, rs, 2);
            rs += __shfl_xor_sync(0xffffffffu, rs, 4);
            rs += __shfl_xor_sync(0xffffffffu, rs, 8);
            l_i[i] += rs;
            #pragma unroll
            for (int j = 0; j < 4; ++j)
                Ps[(ty * 4 + i) * 65 + tx * 4 + j] = s[i][j];
        }
        __syncthreads();

        // ---- O += P V ----
        #pragma unroll 8
        for (int mm = 0; mm < 64; ++mm) {
            float4 v4 = *(float4*)&Vs[mm * 64 + tx * 4];
            float vv[4] = {v4.x, v4.y, v4.z, v4.w};
            float pr[4];
            #pragma unroll
            for (int i = 0; i < 4; ++i) pr[i] = Ps[(ty * 4 + i) * 65 + mm];
            #pragma unroll
            for (int i = 0; i < 4; ++i)
                #pragma unroll
                for (int j = 0; j < 4; ++j)
                    o_i[i][j] += pr[i] * vv[j];
        }
    }

    #pragma unroll
    for (int i = 0; i < 4; ++i) {
        float inv = 1.0f / l_i[i];
        float4 ov = make_float4(o_i[i][0] * inv, o_i[i][1] * inv,
                                o_i[i][2] * inv, o_i[i][3] * inv);
        *(float4*)&g_o[(b * N_ + q0 + ty * 4 + i) * C_ + tx * 4] = ov;
    }
}

// ---------------------------------------------------------------------------
// Proj + bias + residual: out[b,o,n] = sum_c wp[o,c]*O[b,n,c] + bp[o] + x[b,o,n]
// grid (N/64, B), 256 thr
// ---------------------------------------------------------------------------
__global__ __launch_bounds__(256) void proj_kernel(
    const float* __restrict__ x, const float* __restrict__ wp,
    const float* __restrict__ bp, float* __restrict__ out)
{
    const int b  = blockIdx.y;
    const int n0 = blockIdx.x * 64;

    __shared__ float ws[64 * 65];   // [o][c]
    __shared__ float Os[64 * 65];   // [n][c]

    const int t  = threadIdx.x;
    const int tx = t & 15;
    const int ty = t >> 4;

    #pragma unroll
    for (int it = 0; it < 4; ++it) {
        int idx = it * 256 + t;
        int r = idx >> 4, cg = (idx & 15) << 2;
        float4 wv = *(const float4*)&wp[r * C_ + cg];
        ws[r * 65 + cg + 0] = wv.x;
        ws[r * 65 + cg + 1] = wv.y;
        ws[r * 65 + cg + 2] = wv.z;
        ws[r * 65 + cg + 3] = wv.w;
        float4 ov = *(const float4*)&g_o[(b * N_ + n0 + r) * C_ + cg];
        Os[r * 65 + cg + 0] = ov.x;
        Os[r * 65 + cg + 1] = ov.y;
        Os[r * 65 + cg + 2] = ov.z;
        Os[r * 65 + cg + 3] = ov.w;
    }
    __syncthreads();

    float acc[4][4] = {};
    #pragma unroll 8
    for (int c = 0; c < 64; ++c) {
        float wr[4], ov[4];
        #pragma unroll
        for (int i = 0; i < 4; ++i) wr[i] = ws[(ty * 4 + i) * 65 + c];
        #pragma unroll
        for (int j = 0; j < 4; ++j) ov[j] = Os[(tx * 4 + j) * 65 + c];
        #pragma unroll
        for (int i = 0; i < 4; ++i)
            #pragma unroll
            for (int j = 0; j < 4; ++j)
                acc[i][j] += wr[i] * ov[j];
    }

    #pragma unroll
    for (int i = 0; i < 4; ++i) {
        int o = ty * 4 + i;
        float bb = bp[o];
        float4 xv = *(const float4*)&x[(b * C_ + o) * N_ + n0 + tx * 4];
        float4 r4 = make_float4(acc[i][0] + bb + xv.x, acc[i][1] + bb + xv.y,
                                acc[i][2] + bb + xv.z, acc[i][3] + bb + xv.w);
        *(float4*)&out[(b * C_ + o) * N_ + n0 + tx * 4] = r4;
    }
}

// ---------------------------------------------------------------------------
extern "C" void kernel_launch(void* const* d_in, const int* in_sizes, int n_in,
                              void* d_out, int out_size)
{
    const float* x      = (const float*)d_in[0];
    const float* w_qkv  = (const float*)d_in[1];
    const float* b_qkv  = (const float*)d_in[2];
    const float* w_proj = (const float*)d_in[3];
    const float* b_proj = (const float*)d_in[4];
    float* out = (float*)d_out;

    cudaFuncSetAttribute(attn_kernel,
                         cudaFuncAttributeMaxDynamicSharedMemorySize, ATTN_SMEM);

    qkv_kernel<<<dim3(N_ / 64, 3, B_), 256>>>(x, w_qkv, b_qkv);
    attn_kernel<<<dim3(N_ / 64, B_), 256, ATTN_SMEM>>>();
    proj_kernel<<<dim3(N_ / 64, B_), 256>>>(x, w_proj, b_proj, out);
}

// round 7
// speedup vs baseline: 10.9588x; 10.9588x over previous
#include <cuda_runtime.h>
#include <cuda_fp16.h>
#include <cstdint>

#define B_ 4
#define C_ 64
#define N_ 4096

// fp16 scratch + fp32 attention output
__device__ __half g_qh[B_ * N_ * C_]; // [b][n][c], pre-scaled by 0.125*log2e
__device__ __half g_kh[B_ * N_ * C_]; // [b][n][c]
__device__ __half g_vh[B_ * C_ * N_]; // [b][c][n]
__device__ float  g_o [B_ * N_ * C_]; // [b][n][c]

// ---------------------------------------------------------------------------
// helpers (baseline PTX only — must compile for plain sm_103)
// ---------------------------------------------------------------------------
__device__ __forceinline__ uint32_t smem_u32(const void* p) {
    uint32_t a;
    asm("{ .reg .u64 t; cvta.to.shared.u64 t, %1; cvt.u32.u64 %0, t; }"
        : "=r"(a) : "l"(p));
    return a;
}
__device__ __forceinline__ float ex2f(float x) {
    float r; asm("ex2.approx.f32 %0, %1;" : "=f"(r) : "f"(x)); return r;
}
__device__ __forceinline__ uint32_t pack_f16x2(float lo, float hi) {
    uint32_t r;
    asm("cvt.rn.f16x2.f32 %0, %1, %2;" : "=r"(r) : "f"(hi), "f"(lo));
    return r;
}
__device__ __forceinline__ void ldsm4(uint32_t* r, uint32_t a) {
    asm volatile("ldmatrix.sync.aligned.m8n8.x4.shared.b16 {%0,%1,%2,%3}, [%4];"
                 : "=r"(r[0]), "=r"(r[1]), "=r"(r[2]), "=r"(r[3]) : "r"(a));
}
__device__ __forceinline__ void ldsm2(uint32_t* r, uint32_t a) {
    asm volatile("ldmatrix.sync.aligned.m8n8.x2.shared.b16 {%0,%1}, [%2];"
                 : "=r"(r[0]), "=r"(r[1]) : "r"(a));
}
__device__ __forceinline__ void mma16816(float* d, const uint32_t* a,
                                         const uint32_t* b) {
    asm volatile(
        "mma.sync.aligned.m16n8k16.row.col.f32.f16.f16.f32 "
        "{%0,%1,%2,%3}, {%4,%5,%6,%7}, {%8,%9}, {%0,%1,%2,%3};"
        : "+f"(d[0]), "+f"(d[1]), "+f"(d[2]), "+f"(d[3])
        : "r"(a[0]), "r"(a[1]), "r"(a[2]), "r"(a[3]), "r"(b[0]), "r"(b[1]));
}
__device__ __forceinline__ void cp16(uint32_t dst, const void* src) {
    asm volatile("cp.async.cg.shared.global [%0], [%1], 16;"
                 :: "r"(dst), "l"(src));
}
#define CP_COMMIT() asm volatile("cp.async.commit_group;" ::: "memory")
#define CP_WAIT0()  asm volatile("cp.async.wait_group 0;" ::: "memory")
#define SW(o) ((o) ^ (((o) >> 3) & 0x70))

// ---------------------------------------------------------------------------
// QKV: qkv[o,n] = sum_c w[o,c] * x[b,c,n] + bias[o]  -> fp16 outputs
// grid (N/64, 3, B), 256 thr
// ---------------------------------------------------------------------------
__global__ __launch_bounds__(256) void qkv_kernel(
    const float* __restrict__ x, const float* __restrict__ w,
    const float* __restrict__ bias)
{
    const int b  = blockIdx.z;
    const int og = blockIdx.y;
    const int n0 = blockIdx.x * 64;

    __shared__ float xs[64 * 64];
    __shared__ float ws[64 * 65];

    const int t  = threadIdx.x;
    const int tx = t & 15;
    const int ty = t >> 4;

    #pragma unroll
    for (int it = 0; it < 4; ++it) {
        int idx = it * 256 + t;
        int r = idx >> 4, cg = (idx & 15) << 2;
        *(float4*)&xs[r * 64 + cg] = *(const float4*)&x[(b * C_ + r) * N_ + n0 + cg];
        float4 wv = *(const float4*)&w[(og * 64 + r) * C_ + cg];
        ws[r * 65 + cg + 0] = wv.x;
        ws[r * 65 + cg + 1] = wv.y;
        ws[r * 65 + cg + 2] = wv.z;
        ws[r * 65 + cg + 3] = wv.w;
    }
    __syncthreads();

    float acc[4][4] = {};
    #pragma unroll 8
    for (int c = 0; c < 64; ++c) {
        float4 x4 = *(float4*)&xs[c * 64 + tx * 4];
        float xv[4] = {x4.x, x4.y, x4.z, x4.w};
        float wr[4];
        #pragma unroll
        for (int i = 0; i < 4; ++i) wr[i] = ws[(ty * 4 + i) * 65 + c];
        #pragma unroll
        for (int i = 0; i < 4; ++i)
            #pragma unroll
            for (int j = 0; j < 4; ++j)
                acc[i][j] += wr[i] * xv[j];
    }

    float bb[4];
    #pragma unroll
    for (int i = 0; i < 4; ++i) bb[i] = bias[og * 64 + ty * 4 + i];

    if (og < 2) {
        __half* dst = (og == 0) ? g_qh : g_kh;
        const float sc = (og == 0) ? 0.18033688011112042f : 1.0f; // 0.125*log2(e)
        #pragma unroll
        for (int j = 0; j < 4; ++j) {
            int n = n0 + tx * 4 + j;
            size_t base = ((size_t)b * N_ + n) * C_ + ty * 4;
            *(__half2*)&dst[base + 0] =
                __floats2half2_rn((acc[0][j] + bb[0]) * sc, (acc[1][j] + bb[1]) * sc);
            *(__half2*)&dst[base + 2] =
                __floats2half2_rn((acc[2][j] + bb[2]) * sc, (acc[3][j] + bb[3]) * sc);
        }
    } else {
        #pragma unroll
        for (int i = 0; i < 4; ++i) {
            int o = ty * 4 + i;
            size_t base = ((size_t)b * C_ + o) * N_ + n0 + tx * 4;
            *(__half2*)&g_vh[base + 0] = __floats2half2_rn(acc[i][0] + bb[i], acc[i][1] + bb[i]);
            *(__half2*)&g_vh[base + 2] = __floats2half2_rn(acc[i][2] + bb[i], acc[i][3] + bb[i]);
        }
    }
}

// ---------------------------------------------------------------------------
// HMMA flash attention. grid (N/128, B), 256 thr (8 warps, 16 q-rows each).
// SMEM: Q 128x64 fp16 (16KB) | K 2x 64x64 (16KB) | V 2x 64x64 (16KB)
// Non-centered base-2 softmax; P kept in registers (C-frag -> A-frag reuse).
// ---------------------------------------------------------------------------
#define SM_TOT (48 * 1024 + 128)

__global__ __launch_bounds__(256, 1) void attn_mma_kernel()
{
    extern __shared__ char smraw[];
    char* sm = (char*)((((uintptr_t)smraw) + 127) & ~(uintptr_t)127);
    const uint32_t Qb = smem_u32(sm);
    const uint32_t Kb = Qb + 16384;
    const uint32_t Vb = Qb + 32768;

    const int t    = threadIdx.x;
    const int w    = t >> 5;
    const int lane = t & 31;
    const int b    = blockIdx.y;
    const int q0   = blockIdx.x * 128;
    const int m0   = 16 * w;

    const uint4* qp = (const uint4*)g_qh;
    const uint4* kp = (const uint4*)g_kh;
    const uint4* vp = (const uint4*)g_vh;

    // Load Q tile (128 rows x 128B), SW128-swizzled
    #pragma unroll
    for (int u = 0; u < 4; ++u) {
        int e = u * 256 + t, r = e >> 3, ch = e & 7;
        uint32_t off = SW((uint32_t)(r * 128 + ch * 16));
        *(uint4*)(sm + off) = qp[((size_t)(b * N_ + q0 + r) << 3) + ch];
    }
    // cp.async K/V tile 0 into buf 0
    {
        #pragma unroll
        for (int u = 0; u < 2; ++u) {
            int e = u * 256 + t, r = e >> 3, ch = e & 7;
            uint32_t off = SW((uint32_t)(r * 128 + ch * 16));
            cp16(Kb + off, &kp[((size_t)(b * N_ + r) << 3) + ch]);
            cp16(Vb + off, &vp[(((size_t)(b * C_ + r) * N_) >> 3) + ch]);
        }
    }
    CP_COMMIT();
    CP_WAIT0();
    __syncthreads();

    // ldmatrix address components (byte offsets within a tile, pre-swizzle)
    const int a_r  = m0 + (lane & 7) + ((lane >> 3) & 1) * 8;  // A: Q row
    const int a_c8 = ((lane >> 4) & 1) * 8;                    // A: col +8 half
    const int idx  = lane & 15;                                 // B: x2 uses 16 addrs
    const int b_r  = idx & 7;
    const int b_c8 = (idx >> 3) * 8;

    float o[8][4] = {};
    float l0 = 0.f, l1 = 0.f;

    for (int tt = 0; tt < 64; ++tt) {
        const int buf = tt & 1;
        const uint32_t Kt = Kb + buf * 8192;
        const uint32_t Vt = Vb + buf * 8192;

        // issue async copy of next tile into buf^1 (readers of buf^1 finished
        // before the __syncthreads at the end of iteration tt-1)
        if (tt < 63) {
            const int n0 = (tt + 1) * 64;
            const uint32_t Kn = Kb + (buf ^ 1) * 8192;
            const uint32_t Vn = Vb + (buf ^ 1) * 8192;
            #pragma unroll
            for (int u = 0; u < 2; ++u) {
                int e = u * 256 + t, r = e >> 3, ch = e & 7;
                uint32_t off = SW((uint32_t)(r * 128 + ch * 16));
                cp16(Kn + off, &kp[((size_t)(b * N_ + n0 + r) << 3) + ch]);
                cp16(Vn + off, &vp[(((size_t)(b * C_ + r) * N_ + n0) >> 3) + ch]);
            }
        }
        CP_COMMIT();

        // ---- S = Q K^T : 8 n-tiles (8 keys each) x 4 k-steps (16 chans) ----
        float sc[8][4] = {};
        #pragma unroll
        for (int kk = 0; kk < 4; ++kk) {
            uint32_t aq[4];
            ldsm4(aq, Qb + SW((uint32_t)(a_r * 128 + (kk * 16 + a_c8) * 2)));
            #pragma unroll
            for (int j = 0; j < 8; ++j) {
                uint32_t bk[2];
                ldsm2(bk, Kt + SW((uint32_t)((8 * j + b_r) * 128 + (kk * 16 + b_c8) * 2)));
                mma16816(sc[j], aq, bk);
            }
        }

        // ---- softmax (non-centered, base 2) + pack P as A-fragments ----
        uint32_t pa[4][4];
        #pragma unroll
        for (int j = 0; j < 8; ++j) {
            float e0 = ex2f(sc[j][0]);
            float e1 = ex2f(sc[j][1]);
            float e2 = ex2f(sc[j][2]);
            float e3 = ex2f(sc[j][3]);
            l0 += e0 + e1;
            l1 += e2 + e3;
            pa[j >> 1][(j & 1) * 2 + 0] = pack_f16x2(e0, e1);
            pa[j >> 1][(j & 1) * 2 + 1] = pack_f16x2(e2, e3);
        }

        // ---- O += P V : 4 key-steps (16 keys) x 8 channel n-tiles ----
        #pragma unroll
        for (int kk = 0; kk < 4; ++kk) {
            #pragma unroll
            for (int j = 0; j < 8; ++j) {
                uint32_t bv[2];
                ldsm2(bv, Vt + SW((uint32_t)((8 * j + b_r) * 128 + (kk * 16 + b_c8) * 2)));
                mma16816(o[j], pa[kk], bv);
            }
        }

        CP_WAIT0();
        __syncthreads();
    }

    // ---- epilogue: reduce l across quad, normalize, store ----
    l0 += __shfl_xor_sync(0xffffffffu, l0, 1);
    l0 += __shfl_xor_sync(0xffffffffu, l0, 2);
    l1 += __shfl_xor_sync(0xffffffffu, l1, 1);
    l1 += __shfl_xor_sync(0xffffffffu, l1, 2);
    const float inv0 = 1.0f / l0;
    const float inv1 = 1.0f / l1;

    const int g   = lane >> 2;
    const int tig = lane & 3;
    const int qr0 = q0 + m0 + g;
    const int qr1 = qr0 + 8;
    #pragma unroll
    for (int j = 0; j < 8; ++j) {
        int c = 8 * j + 2 * tig;
        *(float2*)&g_o[((size_t)(b * N_ + qr0)) * C_ + c] =
            make_float2(o[j][0] * inv0, o[j][1] * inv0);
        *(float2*)&g_o[((size_t)(b * N_ + qr1)) * C_ + c] =
            make_float2(o[j][2] * inv1, o[j][3] * inv1);
    }
}

// ---------------------------------------------------------------------------
// Proj + bias + residual: out[b,o,n] = sum_c wp[o,c]*O[b,n,c] + bp[o] + x[b,o,n]
// grid (N/64, B), 256 thr
// ---------------------------------------------------------------------------
__global__ __launch_bounds__(256) void proj_kernel(
    const float* __restrict__ x, const float* __restrict__ wp,
    const float* __restrict__ bp, float* __restrict__ out)
{
    const int b  = blockIdx.y;
    const int n0 = blockIdx.x * 64;

    __shared__ float ws[64 * 65];
    __shared__ float Os[64 * 65];

    const int t  = threadIdx.x;
    const int tx = t & 15;
    const int ty = t >> 4;

    #pragma unroll
    for (int it = 0; it < 4; ++it) {
        int idx = it * 256 + t;
        int r = idx >> 4, cg = (idx & 15) << 2;
        float4 wv = *(const float4*)&wp[r * C_ + cg];
        ws[r * 65 + cg + 0] = wv.x;
        ws[r * 65 + cg + 1] = wv.y;
        ws[r * 65 + cg + 2] = wv.z;
        ws[r * 65 + cg + 3] = wv.w;
        float4 ov = *(const float4*)&g_o[((size_t)b * N_ + n0 + r) * C_ + cg];
        Os[r * 65 + cg + 0] = ov.x;
        Os[r * 65 + cg + 1] = ov.y;
        Os[r * 65 + cg + 2] = ov.z;
        Os[r * 65 + cg + 3] = ov.w;
    }
    __syncthreads();

    float acc[4][4] = {};
    #pragma unroll 8
    for (int c = 0; c < 64; ++c) {
        float wr[4], ov[4];
        #pragma unroll
        for (int i = 0; i < 4; ++i) wr[i] = ws[(ty * 4 + i) * 65 + c];
        #pragma unroll
        for (int j = 0; j < 4; ++j) ov[j] = Os[(tx * 4 + j) * 65 + c];
        #pragma unroll
        for (int i = 0; i < 4; ++i)
            #pragma unroll
            for (int j = 0; j < 4; ++j)
                acc[i][j] += wr[i] * ov[j];
    }

    #pragma unroll
    for (int i = 0; i < 4; ++i) {
        int o = ty * 4 + i;
        float bb = bp[o];
        float4 xv = *(const float4*)&x[(b * C_ + o) * N_ + n0 + tx * 4];
        float4 r4 = make_float4(acc[i][0] + bb + xv.x, acc[i][1] + bb + xv.y,
                                acc[i][2] + bb + xv.z, acc[i][3] + bb + xv.w);
        *(float4*)&out[(b * C_ + o) * N_ + n0 + tx * 4] = r4;
    }
}

// ---------------------------------------------------------------------------
extern "C" void kernel_launch(void* const* d_in, const int* in_sizes, int n_in,
                              void* d_out, int out_size)
{
    const float* x      = (const float*)d_in[0];
    const float* w_qkv  = (const float*)d_in[1];
    const float* b_qkv  = (const float*)d_in[2];
    const float* w_proj = (const float*)d_in[3];
    const float* b_proj = (const float*)d_in[4];
    float* out = (float*)d_out;

    cudaFuncSetAttribute(attn_mma_kernel,
                         cudaFuncAttributeMaxDynamicSharedMemorySize, SM_TOT);

    qkv_kernel<<<dim3(N_ / 64, 3, B_), 256>>>(x, w_qkv, b_qkv);
    attn_mma_kernel<<<dim3(N_ / 128, B_), 256, SM_TOT>>>();
    proj_kernel<<<dim3(N_ / 64, B_), 256>>>(x, w_proj, b_proj, out);
}

// round 8
// speedup vs baseline: 13.8133x; 1.2605x over previous
#include <cuda_runtime.h>
#include <cuda_fp16.h>
#include <cstdint>

#define B_ 4
#define C_ 64
#define N_ 4096

// fp16 scratch
__device__ __half g_qh[B_ * N_ * C_]; // [b][n][c], pre-scaled by 0.125*log2e
__device__ __half g_kh[B_ * N_ * C_]; // [b][n][c]
__device__ __half g_vh[B_ * C_ * N_]; // [b][c][n]
__device__ __half g_oh[B_ * N_ * C_]; // [b][n][c]

// ---------------------------------------------------------------------------
// helpers (baseline PTX only — must compile for plain sm_103)
// ---------------------------------------------------------------------------
__device__ __forceinline__ uint32_t smem_u32(const void* p) {
    uint32_t a;
    asm("{ .reg .u64 t; cvta.to.shared.u64 t, %1; cvt.u32.u64 %0, t; }"
        : "=r"(a) : "l"(p));
    return a;
}
__device__ __forceinline__ float ex2f(float x) {
    float r; asm("ex2.approx.f32 %0, %1;" : "=f"(r) : "f"(x)); return r;
}
__device__ __forceinline__ uint32_t pack_f16x2(float lo, float hi) {
    uint32_t r;
    asm("cvt.rn.f16x2.f32 %0, %1, %2;" : "=r"(r) : "f"(hi), "f"(lo));
    return r;
}
__device__ __forceinline__ void ldsm4(uint32_t* r, uint32_t a) {
    asm volatile("ldmatrix.sync.aligned.m8n8.x4.shared.b16 {%0,%1,%2,%3}, [%4];"
                 : "=r"(r[0]), "=r"(r[1]), "=r"(r[2]), "=r"(r[3]) : "r"(a));
}
__device__ __forceinline__ void ldsm4t(uint32_t* r, uint32_t a) {
    asm volatile("ldmatrix.sync.aligned.m8n8.x4.trans.shared.b16 {%0,%1,%2,%3}, [%4];"
                 : "=r"(r[0]), "=r"(r[1]), "=r"(r[2]), "=r"(r[3]) : "r"(a));
}
__device__ __forceinline__ void mma16816(float* d, const uint32_t* a,
                                         const uint32_t* b) {
    asm volatile(
        "mma.sync.aligned.m16n8k16.row.col.f32.f16.f16.f32 "
        "{%0,%1,%2,%3}, {%4,%5,%6,%7}, {%8,%9}, {%0,%1,%2,%3};"
        : "+f"(d[0]), "+f"(d[1]), "+f"(d[2]), "+f"(d[3])
        : "r"(a[0]), "r"(a[1]), "r"(a[2]), "r"(a[3]), "r"(b[0]), "r"(b[1]));
}
__device__ __forceinline__ void cp16(uint32_t dst, const void* src) {
    asm volatile("cp.async.cg.shared.global [%0], [%1], 16;"
                 :: "r"(dst), "l"(src));
}
#define CP_COMMIT() asm volatile("cp.async.commit_group;" ::: "memory")
#define CP_WAIT0()  asm volatile("cp.async.wait_group 0;" ::: "memory")
#define SW(o) ((o) ^ (((o) >> 3) & 0x70))
#define QK_SCALE 0.18033688011112042f  // 0.125 * log2(e)

// ---------------------------------------------------------------------------
// QKV via HMMA. grid (N/128, B), 256 thr (8 warps; warp w owns 16 n-rows).
// out[n][o] = sum_c x^T[n][c] * w[o][c];  A = x^T via ldmatrix.trans,
// B = w rows (K-style).  q,k stored [b][n][c] fp16; v transposed to [b][c][n]
// via smem staging (vt aliases dead ws/xs).
// ---------------------------------------------------------------------------
__global__ __launch_bounds__(256) void qkv_mma_kernel(
    const float* __restrict__ x, const float* __restrict__ w,
    const float* __restrict__ bias)
{
    static __shared__ __align__(128) char smq[24576 + 16384 + 768];
    char* ws = smq;                     // [o 192][c 64] fp16, SW128 rows
    char* xs = smq + 24576;             // [c 64][n 128] fp16, 256B rows, chunk-XOR
    float* bs = (float*)(smq + 40960);  // bias[192]
    const uint32_t ws_b = smem_u32(ws);
    const uint32_t xs_b = smem_u32(xs);

    const int t    = threadIdx.x;
    const int wrp  = t >> 5;
    const int lane = t & 31;
    const int b    = blockIdx.y;
    const int n0   = blockIdx.x * 128;
    const int m0   = 16 * wrp;

    // load w (192x64 fp32 -> fp16 SW128 rows of 128B)
    #pragma unroll
    for (int u = 0; u < 6; ++u) {
        int e = u * 256 + t, o = e >> 3, ch = e & 7;
        float4 w0 = *(const float4*)&w[o * 64 + ch * 8];
        float4 w1 = *(const float4*)&w[o * 64 + ch * 8 + 4];
        uint4 hv;
        hv.x = pack_f16x2(w0.x, w0.y);
        hv.y = pack_f16x2(w0.z, w0.w);
        hv.z = pack_f16x2(w1.x, w1.y);
        hv.w = pack_f16x2(w1.z, w1.w);
        *(uint4*)(ws + SW((uint32_t)(o * 128 + ch * 16))) = hv;
    }
    // load x tile (64c x 128n fp32 -> fp16), rows 256B, chunk = nch ^ (c&7)
    #pragma unroll
    for (int u = 0; u < 4; ++u) {
        int e = u * 256 + t, c = e >> 4, nch = e & 15;
        const float* xp = &x[((size_t)(b * C_ + c)) * N_ + n0 + nch * 8];
        float4 x0 = *(const float4*)xp;
        float4 x1 = *(const float4*)(xp + 4);
        uint4 hv;
        hv.x = pack_f16x2(x0.x, x0.y);
        hv.y = pack_f16x2(x0.z, x0.w);
        hv.z = pack_f16x2(x1.x, x1.y);
        hv.w = pack_f16x2(x1.z, x1.w);
        *(uint4*)(xs + (uint32_t)(c * 256 + ((nch ^ (c & 7)) << 4))) = hv;
    }
    if (t < 192) bs[t] = bias[t];
    __syncthreads();

    // A fragments (x^T) via ldmatrix.trans
    uint32_t aq[4][4];
    {
        const int c_l   = (lane & 7) + ((lane >> 4) & 1) * 8;
        const int chunk = ((m0 >> 3) + ((lane >> 3) & 1)) ^ (lane & 7);
        #pragma unroll
        for (int kk = 0; kk < 4; ++kk)
            ldsm4t(aq[kk], xs_b + (uint32_t)((kk * 16 + c_l) * 256 + chunk * 16));
    }

    // B fragments (w) + 96 MMAs
    float acc[24][4] = {};
    const int prow = (lane & 7) + ((lane >> 4) & 1) * 8;
    const int pc8  = ((lane >> 3) & 1) * 8;
    #pragma unroll
    for (int kk = 0; kk < 4; ++kk) {
        #pragma unroll
        for (int jp = 0; jp < 12; ++jp) {
            uint32_t bw[4];
            ldsm4(bw, ws_b + SW((uint32_t)((16 * jp + prow) * 128 + (kk * 16 + pc8) * 2)));
            mma16816(acc[2 * jp], aq[kk], bw);
            mma16816(acc[2 * jp + 1], aq[kk], bw + 2);
        }
    }

    // epilogue
    const int g   = lane >> 2;
    const int tig = lane & 3;
    const int n_a = n0 + m0 + g;
    const int n_b = n_a + 8;
    #pragma unroll
    for (int j = 0; j < 8; ++j) {   // q (scaled)
        int o = 8 * j + 2 * tig;
        float b0 = bs[o], b1 = bs[o + 1];
        *(uint32_t*)&g_qh[((size_t)(b * N_ + n_a)) * C_ + o] =
            pack_f16x2((acc[j][0] + b0) * QK_SCALE, (acc[j][1] + b1) * QK_SCALE);
        *(uint32_t*)&g_qh[((size_t)(b * N_ + n_b)) * C_ + o] =
            pack_f16x2((acc[j][2] + b0) * QK_SCALE, (acc[j][3] + b1) * QK_SCALE);
    }
    #pragma unroll
    for (int j = 8; j < 16; ++j) {  // k
        int o = 8 * (j - 8) + 2 * tig;
        float b0 = bs[64 + o], b1 = bs[64 + o + 1];
        *(uint32_t*)&g_kh[((size_t)(b * N_ + n_a)) * C_ + o] =
            pack_f16x2(acc[j][0] + b0, acc[j][1] + b1);
        *(uint32_t*)&g_kh[((size_t)(b * N_ + n_b)) * C_ + o] =
            pack_f16x2(acc[j][2] + b0, acc[j][3] + b1);
    }
    __syncthreads();                 // ws/xs dead -> reuse as vt
    __half* vt = (__half*)smq;       // [o 64][n 128] pitch 136 halves
    #pragma unroll
    for (int j = 16; j < 24; ++j) {  // v -> vt
        int o = 8 * (j - 16) + 2 * tig;
        float b0 = bs[128 + o], b1 = bs[128 + o + 1];
        int na = m0 + g, nb = na + 8;
        vt[o * 136 + na]       = __float2half(acc[j][0] + b0);
        vt[(o + 1) * 136 + na] = __float2half(acc[j][1] + b1);
        vt[o * 136 + nb]       = __float2half(acc[j][2] + b0);
        vt[(o + 1) * 136 + nb] = __float2half(acc[j][3] + b1);
    }
    __syncthreads();
    #pragma unroll
    for (int u = 0; u < 4; ++u) {    // coalesced store v [c][n]
        int e = u * 256 + t, r = e >> 4, ch = e & 15;
        uint4 val = *(uint4*)&vt[r * 136 + ch * 8];
        *(uint4*)&g_vh[((size_t)(b * C_ + r)) * N_ + n0 + ch * 8] = val;
    }
}

// ---------------------------------------------------------------------------
// HMMA flash attention. grid (N/128, B), 256 thr (8 warps, 16 q-rows each).
// Q fragments hoisted; K/V B-frags in n-tile pairs via ldsm.x4.
// Non-centered base-2 softmax; P stays in registers; O stored fp16.
// ---------------------------------------------------------------------------
#define SM_TOT (48 * 1024 + 128)

__global__ __launch_bounds__(256, 1) void attn_mma_kernel()
{
    extern __shared__ char smraw[];
    char* sm = (char*)((((uintptr_t)smraw) + 127) & ~(uintptr_t)127);
    const uint32_t Qb = smem_u32(sm);
    const uint32_t Kb = Qb + 16384;
    const uint32_t Vb = Qb + 32768;

    const int t    = threadIdx.x;
    const int w    = t >> 5;
    const int lane = t & 31;
    const int b    = blockIdx.y;
    const int q0   = blockIdx.x * 128;
    const int m0   = 16 * w;

    const uint4* qp = (const uint4*)g_qh;
    const uint4* kp = (const uint4*)g_kh;
    const uint4* vp = (const uint4*)g_vh;

    // Load Q tile (128 rows x 128B), SW128-swizzled
    #pragma unroll
    for (int u = 0; u < 4; ++u) {
        int e = u * 256 + t, r = e >> 3, ch = e & 7;
        uint32_t off = SW((uint32_t)(r * 128 + ch * 16));
        *(uint4*)(sm + off) = qp[((size_t)(b * N_ + q0 + r) << 3) + ch];
    }
    // cp.async K/V tile 0 into buf 0
    #pragma unroll
    for (int u = 0; u < 2; ++u) {
        int e = u * 256 + t, r = e >> 3, ch = e & 7;
        uint32_t off = SW((uint32_t)(r * 128 + ch * 16));
        cp16(Kb + off, &kp[((size_t)(b * N_ + r) << 3) + ch]);
        cp16(Vb + off, &vp[(((size_t)(b * C_ + r) * N_) >> 3) + ch]);
    }
    CP_COMMIT();
    CP_WAIT0();
    __syncthreads();

    // Hoist Q A-fragments (loop-invariant)
    uint32_t aq[4][4];
    {
        const int a_r  = m0 + (lane & 7) + ((lane >> 3) & 1) * 8;
        const int a_c8 = ((lane >> 4) & 1) * 8;
        #pragma unroll
        for (int kk = 0; kk < 4; ++kk)
            ldsm4(aq[kk], Qb + SW((uint32_t)(a_r * 128 + (kk * 16 + a_c8) * 2)));
    }

    // paired-B ldsm.x4 address components
    const int prow = (lane & 7) + ((lane >> 4) & 1) * 8;
    const int pc8  = ((lane >> 3) & 1) * 8;

    float o[8][4] = {};
    float l0 = 0.f, l1 = 0.f;

    for (int tt = 0; tt < 64; ++tt) {
        const int buf = tt & 1;
        const uint32_t Kt = Kb + buf * 8192;
        const uint32_t Vt = Vb + buf * 8192;

        if (tt < 63) {
            const int n0 = (tt + 1) * 64;
            const uint32_t Kn = Kb + (buf ^ 1) * 8192;
            const uint32_t Vn = Vb + (buf ^ 1) * 8192;
            #pragma unroll
            for (int u = 0; u < 2; ++u) {
                int e = u * 256 + t, r = e >> 3, ch = e & 7;
                uint32_t off = SW((uint32_t)(r * 128 + ch * 16));
                cp16(Kn + off, &kp[((size_t)(b * N_ + n0 + r) << 3) + ch]);
                cp16(Vn + off, &vp[(((size_t)(b * C_ + r) * N_ + n0) >> 3) + ch]);
            }
        }
        CP_COMMIT();

        // ---- S = Q K^T ----
        float sc[8][4] = {};
        #pragma unroll
        for (int kk = 0; kk < 4; ++kk) {
            #pragma unroll
            for (int jp = 0; jp < 4; ++jp) {
                uint32_t bk[4];
                ldsm4(bk, Kt + SW((uint32_t)((16 * jp + prow) * 128 + (kk * 16 + pc8) * 2)));
                mma16816(sc[2 * jp], aq[kk], bk);
                mma16816(sc[2 * jp + 1], aq[kk], bk + 2);
            }
        }

        // ---- softmax (non-centered, base 2) + pack P as A-fragments ----
        uint32_t pa[4][4];
        #pragma unroll
        for (int j = 0; j < 8; ++j) {
            float e0 = ex2f(sc[j][0]);
            float e1 = ex2f(sc[j][1]);
            float e2 = ex2f(sc[j][2]);
            float e3 = ex2f(sc[j][3]);
            l0 += e0 + e1;
            l1 += e2 + e3;
            pa[j >> 1][(j & 1) * 2 + 0] = pack_f16x2(e0, e1);
            pa[j >> 1][(j & 1) * 2 + 1] = pack_f16x2(e2, e3);
        }

        // ---- O += P V ----
        #pragma unroll
        for (int kk = 0; kk < 4; ++kk) {
            #pragma unroll
            for (int jp = 0; jp < 4; ++jp) {
                uint32_t bv[4];
                ldsm4(bv, Vt + SW((uint32_t)((16 * jp + prow) * 128 + (kk * 16 + pc8) * 2)));
                mma16816(o[2 * jp], pa[kk], bv);
                mma16816(o[2 * jp + 1], pa[kk], bv + 2);
            }
        }

        CP_WAIT0();
        __syncthreads();
    }

    // ---- epilogue: reduce l across quad, normalize, store fp16 ----
    l0 += __shfl_xor_sync(0xffffffffu, l0, 1);
    l0 += __shfl_xor_sync(0xffffffffu, l0, 2);
    l1 += __shfl_xor_sync(0xffffffffu, l1, 1);
    l1 += __shfl_xor_sync(0xffffffffu, l1, 2);
    const float inv0 = 1.0f / l0;
    const float inv1 = 1.0f / l1;

    const int g   = lane >> 2;
    const int tig = lane & 3;
    const int qr0 = q0 + m0 + g;
    const int qr1 = qr0 + 8;
    #pragma unroll
    for (int j = 0; j < 8; ++j) {
        int c = 8 * j + 2 * tig;
        *(uint32_t*)&g_oh[((size_t)(b * N_ + qr0)) * C_ + c] =
            pack_f16x2(o[j][0] * inv0, o[j][1] * inv0);
        *(uint32_t*)&g_oh[((size_t)(b * N_ + qr1)) * C_ + c] =
            pack_f16x2(o[j][2] * inv1, o[j][3] * inv1);
    }
}

// ---------------------------------------------------------------------------
// Proj + bias + residual: out[b,o,n] = sum_c wp[o,c]*O[b,n,c] + bp[o] + x[b,o,n]
// grid (N/64, B), 256 thr
// ---------------------------------------------------------------------------
__global__ __launch_bounds__(256) void proj_kernel(
    const float* __restrict__ x, const float* __restrict__ wp,
    const float* __restrict__ bp, float* __restrict__ out)
{
    const int b  = blockIdx.y;
    const int n0 = blockIdx.x * 64;

    __shared__ float ws[64 * 65];
    __shared__ float Os[64 * 65];

    const int t  = threadIdx.x;
    const int tx = t & 15;
    const int ty = t >> 4;

    #pragma unroll
    for (int it = 0; it < 4; ++it) {
        int idx = it * 256 + t;
        int r = idx >> 4, cg = (idx & 15) << 2;
        float4 wv = *(const float4*)&wp[r * C_ + cg];
        ws[r * 65 + cg + 0] = wv.x;
        ws[r * 65 + cg + 1] = wv.y;
        ws[r * 65 + cg + 2] = wv.z;
        ws[r * 65 + cg + 3] = wv.w;
        const __half2* op = (const __half2*)&g_oh[((size_t)b * N_ + n0 + r) * C_ + cg];
        float2 o0 = __half22float2(op[0]);
        float2 o1 = __half22float2(op[1]);
        Os[r * 65 + cg + 0] = o0.x;
        Os[r * 65 + cg + 1] = o0.y;
        Os[r * 65 + cg + 2] = o1.x;
        Os[r * 65 + cg + 3] = o1.y;
    }
    __syncthreads();

    float acc[4][4] = {};
    #pragma unroll 8
    for (int c = 0; c < 64; ++c) {
        float wr[4], ov[4];
        #pragma unroll
        for (int i = 0; i < 4; ++i) wr[i] = ws[(ty * 4 + i) * 65 + c];
        #pragma unroll
        for (int j = 0; j < 4; ++j) ov[j] = Os[(tx * 4 + j) * 65 + c];
        #pragma unroll
        for (int i = 0; i < 4; ++i)
            #pragma unroll
            for (int j = 0; j < 4; ++j)
                acc[i][j] += wr[i] * ov[j];
    }

    #pragma unroll
    for (int i = 0; i < 4; ++i) {
        int o = ty * 4 + i;
        float bb = bp[o];
        float4 xv = *(const float4*)&x[(b * C_ + o) * N_ + n0 + tx * 4];
        float4 r4 = make_float4(acc[i][0] + bb + xv.x, acc[i][1] + bb + xv.y,
                                acc[i][2] + bb + xv.z, acc[i][3] + bb + xv.w);
        *(float4*)&out[(b * C_ + o) * N_ + n0 + tx * 4] = r4;
    }
}

// ---------------------------------------------------------------------------
extern "C" void kernel_launch(void* const* d_in, const int* in_sizes, int n_in,
                              void* d_out, int out_size)
{
    const float* x      = (const float*)d_in[0];
    const float* w_qkv  = (const float*)d_in[1];
    const float* b_qkv  = (const float*)d_in[2];
    const float* w_proj = (const float*)d_in[3];
    const float* b_proj = (const float*)d_in[4];
    float* out = (float*)d_out;

    cudaFuncSetAttribute(attn_mma_kernel,
                         cudaFuncAttributeMaxDynamicSharedMemorySize, SM_TOT);

    qkv_mma_kernel<<<dim3(N_ / 128, B_), 256>>>(x, w_qkv, b_qkv);
    attn_mma_kernel<<<dim3(N_ / 128, B_), 256, SM_TOT>>>();
    proj_kernel<<<dim3(N_ / 64, B_), 256>>>(x, w_proj, b_proj, out);
}

// round 9
// speedup vs baseline: 15.5040x; 1.1224x over previous
#include <cuda_runtime.h>
#include <cuda_fp16.h>
#include <cstdint>

#define B_ 4
#define C_ 64
#define N_ 4096

// fp16 scratch
__device__ __half g_qh[B_ * N_ * C_]; // [b][n][c], pre-scaled by 0.125*log2e
__device__ __half g_kh[B_ * N_ * C_]; // [b][n][c]
__device__ __half g_vh[B_ * C_ * N_]; // [b][c][n]

// ---------------------------------------------------------------------------
// helpers (baseline PTX only — must compile for plain sm_103)
// ---------------------------------------------------------------------------
__device__ __forceinline__ uint32_t smem_u32(const void* p) {
    uint32_t a;
    asm("{ .reg .u64 t; cvta.to.shared.u64 t, %1; cvt.u32.u64 %0, t; }"
        : "=r"(a) : "l"(p));
    return a;
}
__device__ __forceinline__ float ex2f(float x) {
    float r; asm("ex2.approx.f32 %0, %1;" : "=f"(r) : "f"(x)); return r;
}
__device__ __forceinline__ uint32_t pack_f16x2(float lo, float hi) {
    uint32_t r;
    asm("cvt.rn.f16x2.f32 %0, %1, %2;" : "=r"(r) : "f"(hi), "f"(lo));
    return r;
}
__device__ __forceinline__ void ldsm4(uint32_t* r, uint32_t a) {
    asm volatile("ldmatrix.sync.aligned.m8n8.x4.shared.b16 {%0,%1,%2,%3}, [%4];"
                 : "=r"(r[0]), "=r"(r[1]), "=r"(r[2]), "=r"(r[3]) : "r"(a));
}
__device__ __forceinline__ void ldsm4t(uint32_t* r, uint32_t a) {
    asm volatile("ldmatrix.sync.aligned.m8n8.x4.trans.shared.b16 {%0,%1,%2,%3}, [%4];"
                 : "=r"(r[0]), "=r"(r[1]), "=r"(r[2]), "=r"(r[3]) : "r"(a));
}
__device__ __forceinline__ void mma16816(float* d, const uint32_t* a,
                                         const uint32_t* b) {
    asm volatile(
        "mma.sync.aligned.m16n8k16.row.col.f32.f16.f16.f32 "
        "{%0,%1,%2,%3}, {%4,%5,%6,%7}, {%8,%9}, {%0,%1,%2,%3};"
        : "+f"(d[0]), "+f"(d[1]), "+f"(d[2]), "+f"(d[3])
        : "r"(a[0]), "r"(a[1]), "r"(a[2]), "r"(a[3]), "r"(b[0]), "r"(b[1]));
}
__device__ __forceinline__ void cp16(uint32_t dst, const void* src) {
    asm volatile("cp.async.cg.shared.global [%0], [%1], 16;"
                 :: "r"(dst), "l"(src));
}
#define CP_COMMIT() asm volatile("cp.async.commit_group;" ::: "memory")
#define CP_WAIT0()  asm volatile("cp.async.wait_group 0;" ::: "memory")
#define SW(o) ((o) ^ (((o) >> 3) & 0x70))
#define QK_SCALE 0.18033688011112042f  // 0.125 * log2(e)

// ---------------------------------------------------------------------------
// QKV via HMMA (unchanged from R7). grid (N/128, B), 256 thr.
// ---------------------------------------------------------------------------
__global__ __launch_bounds__(256) void qkv_mma_kernel(
    const float* __restrict__ x, const float* __restrict__ w,
    const float* __restrict__ bias)
{
    static __shared__ __align__(128) char smq[24576 + 16384 + 768];
    char* ws = smq;                     // [o 192][c 64] fp16, SW128 rows
    char* xs = smq + 24576;             // [c 64][n 128] fp16, 256B rows, chunk-XOR
    float* bs = (float*)(smq + 40960);  // bias[192]
    const uint32_t ws_b = smem_u32(ws);
    const uint32_t xs_b = smem_u32(xs);

    const int t    = threadIdx.x;
    const int wrp  = t >> 5;
    const int lane = t & 31;
    const int b    = blockIdx.y;
    const int n0   = blockIdx.x * 128;
    const int m0   = 16 * wrp;

    #pragma unroll
    for (int u = 0; u < 6; ++u) {
        int e = u * 256 + t, o = e >> 3, ch = e & 7;
        float4 w0 = *(const float4*)&w[o * 64 + ch * 8];
        float4 w1 = *(const float4*)&w[o * 64 + ch * 8 + 4];
        uint4 hv;
        hv.x = pack_f16x2(w0.x, w0.y);
        hv.y = pack_f16x2(w0.z, w0.w);
        hv.z = pack_f16x2(w1.x, w1.y);
        hv.w = pack_f16x2(w1.z, w1.w);
        *(uint4*)(ws + SW((uint32_t)(o * 128 + ch * 16))) = hv;
    }
    #pragma unroll
    for (int u = 0; u < 4; ++u) {
        int e = u * 256 + t, c = e >> 4, nch = e & 15;
        const float* xp = &x[((size_t)(b * C_ + c)) * N_ + n0 + nch * 8];
        float4 x0 = *(const float4*)xp;
        float4 x1 = *(const float4*)(xp + 4);
        uint4 hv;
        hv.x = pack_f16x2(x0.x, x0.y);
        hv.y = pack_f16x2(x0.z, x0.w);
        hv.z = pack_f16x2(x1.x, x1.y);
        hv.w = pack_f16x2(x1.z, x1.w);
        *(uint4*)(xs + (uint32_t)(c * 256 + ((nch ^ (c & 7)) << 4))) = hv;
    }
    if (t < 192) bs[t] = bias[t];
    __syncthreads();

    uint32_t aq[4][4];
    {
        const int c_l   = (lane & 7) + ((lane >> 4) & 1) * 8;
        const int chunk = ((m0 >> 3) + ((lane >> 3) & 1)) ^ (lane & 7);
        #pragma unroll
        for (int kk = 0; kk < 4; ++kk)
            ldsm4t(aq[kk], xs_b + (uint32_t)((kk * 16 + c_l) * 256 + chunk * 16));
    }

    float acc[24][4] = {};
    const int prow = (lane & 7) + ((lane >> 4) & 1) * 8;
    const int pc8  = ((lane >> 3) & 1) * 8;
    #pragma unroll
    for (int kk = 0; kk < 4; ++kk) {
        #pragma unroll
        for (int jp = 0; jp < 12; ++jp) {
            uint32_t bw[4];
            ldsm4(bw, ws_b + SW((uint32_t)((16 * jp + prow) * 128 + (kk * 16 + pc8) * 2)));
            mma16816(acc[2 * jp], aq[kk], bw);
            mma16816(acc[2 * jp + 1], aq[kk], bw + 2);
        }
    }

    const int g   = lane >> 2;
    const int tig = lane & 3;
    const int n_a = n0 + m0 + g;
    const int n_b = n_a + 8;
    #pragma unroll
    for (int j = 0; j < 8; ++j) {   // q (scaled)
        int o = 8 * j + 2 * tig;
        float b0 = bs[o], b1 = bs[o + 1];
        *(uint32_t*)&g_qh[((size_t)(b * N_ + n_a)) * C_ + o] =
            pack_f16x2((acc[j][0] + b0) * QK_SCALE, (acc[j][1] + b1) * QK_SCALE);
        *(uint32_t*)&g_qh[((size_t)(b * N_ + n_b)) * C_ + o] =
            pack_f16x2((acc[j][2] + b0) * QK_SCALE, (acc[j][3] + b1) * QK_SCALE);
    }
    #pragma unroll
    for (int j = 8; j < 16; ++j) {  // k
        int o = 8 * (j - 8) + 2 * tig;
        float b0 = bs[64 + o], b1 = bs[64 + o + 1];
        *(uint32_t*)&g_kh[((size_t)(b * N_ + n_a)) * C_ + o] =
            pack_f16x2(acc[j][0] + b0, acc[j][1] + b1);
        *(uint32_t*)&g_kh[((size_t)(b * N_ + n_b)) * C_ + o] =
            pack_f16x2(acc[j][2] + b0, acc[j][3] + b1);
    }
    __syncthreads();
    __half* vt = (__half*)smq;       // [o 64][n 128] pitch 136
    #pragma unroll
    for (int j = 16; j < 24; ++j) {  // v -> vt
        int o = 8 * (j - 16) + 2 * tig;
        float b0 = bs[128 + o], b1 = bs[128 + o + 1];
        int na = m0 + g, nb = na + 8;
        vt[o * 136 + na]       = __float2half(acc[j][0] + b0);
        vt[(o + 1) * 136 + na] = __float2half(acc[j][1] + b1);
        vt[o * 136 + nb]       = __float2half(acc[j][2] + b0);
        vt[(o + 1) * 136 + nb] = __float2half(acc[j][3] + b1);
    }
    __syncthreads();
    #pragma unroll
    for (int u = 0; u < 4; ++u) {
        int e = u * 256 + t, r = e >> 4, ch = e & 15;
        uint4 val = *(uint4*)&vt[r * 136 + ch * 8];
        *(uint4*)&g_vh[((size_t)(b * C_ + r)) * N_ + n0 + ch * 8] = val;
    }
}

// ---------------------------------------------------------------------------
// Fused HMMA flash attention + projection + residual. grid (N/128, B), 256 thr.
// Warp w: m-block mb=w&3 (32 q-rows = 2 m16 tiles), key-half nh=w>>2.
// Each warp reads only its key-half of K/V (halves smem traffic).
// End: cross-warp O/l reduction -> fp16 O tile in smem -> proj HMMA -> d_out.
// SMEM map (bytes):
//   [0,16384)      Q tile fp16 SW128 (dead after loop -> reused as Os16)
//   [16384,49152)  K,V double buffers (dead after loop -> aliased by Ored)
//   Ored fp32 128x66 @16384..50176
//   [50176,58368)  wp fp16 SW128
//   [58368,58880)  lred fp32[128]
//   [58880,59136)  bias fp32[64]
// ---------------------------------------------------------------------------
#define SM_TOT (59392 + 128)

__global__ __launch_bounds__(256, 1) void attn_proj_kernel(
    const float* __restrict__ x, const float* __restrict__ wp,
    const float* __restrict__ bp, float* __restrict__ out)
{
    extern __shared__ char smraw[];
    char* sm = (char*)((((uintptr_t)smraw) + 127) & ~(uintptr_t)127);
    const uint32_t Qb = smem_u32(sm);
    const uint32_t Kb = Qb + 16384;
    const uint32_t Vb = Qb + 32768;
    const uint32_t Wb = Qb + 50176;
    float* Ored = (float*)(sm + 16384);   // pitch 66 floats
    float* lred = (float*)(sm + 58368);
    float* bs   = (float*)(sm + 58880);

    const int t    = threadIdx.x;
    const int w    = t >> 5;
    const int lane = t & 31;
    const int b    = blockIdx.y;
    const int q0   = blockIdx.x * 128;
    const int mb   = w & 3;
    const int nh   = w >> 2;

    const uint4* qp = (const uint4*)g_qh;
    const uint4* kp = (const uint4*)g_kh;
    const uint4* vp = (const uint4*)g_vh;

    // Load Q tile (128 rows x 128B), SW128-swizzled
    #pragma unroll
    for (int u = 0; u < 4; ++u) {
        int e = u * 256 + t, r = e >> 3, ch = e & 7;
        uint32_t off = SW((uint32_t)(r * 128 + ch * 16));
        *(uint4*)(sm + off) = qp[((size_t)(b * N_ + q0 + r) << 3) + ch];
    }
    // Load wp (64x64 fp32 -> fp16 SW128 rows)
    #pragma unroll
    for (int u = 0; u < 2; ++u) {
        int e = u * 256 + t, o = e >> 3, ch = e & 7;
        float4 w0 = *(const float4*)&wp[o * 64 + ch * 8];
        float4 w1 = *(const float4*)&wp[o * 64 + ch * 8 + 4];
        uint4 hv;
        hv.x = pack_f16x2(w0.x, w0.y);
        hv.y = pack_f16x2(w0.z, w0.w);
        hv.z = pack_f16x2(w1.x, w1.y);
        hv.w = pack_f16x2(w1.z, w1.w);
        *(uint4*)(sm + (Wb - Qb) + SW((uint32_t)(o * 128 + ch * 16))) = hv;
    }
    if (t < 64) bs[t] = bp[t];
    // cp.async K/V tile 0 into buf 0
    #pragma unroll
    for (int u = 0; u < 2; ++u) {
        int e = u * 256 + t, r = e >> 3, ch = e & 7;
        uint32_t off = SW((uint32_t)(r * 128 + ch * 16));
        cp16(Kb + off, &kp[((size_t)(b * N_ + r) << 3) + ch]);
        cp16(Vb + off, &vp[(((size_t)(b * C_ + r) * N_) >> 3) + ch]);
    }
    CP_COMMIT();
    CP_WAIT0();
    __syncthreads();

    // Hoist Q A-fragments: 2 m16 tiles of this warp's 32 rows
    uint32_t aq[2][4][4];
    {
        const int a_c8 = ((lane >> 4) & 1) * 8;
        #pragma unroll
        for (int mt = 0; mt < 2; ++mt) {
            const int a_r = 32 * mb + 16 * mt + (lane & 7) + ((lane >> 3) & 1) * 8;
            #pragma unroll
            for (int kk = 0; kk < 4; ++kk)
                ldsm4(aq[mt][kk], Qb + SW((uint32_t)(a_r * 128 + (kk * 16 + a_c8) * 2)));
        }
    }

    const int prow = (lane & 7) + ((lane >> 4) & 1) * 8;
    const int pc8  = ((lane >> 3) & 1) * 8;

    float o[2][8][4] = {};
    float l0[2] = {0.f, 0.f}, l1[2] = {0.f, 0.f};

    for (int tt = 0; tt < 64; ++tt) {
        const int buf = tt & 1;
        const uint32_t Kt = Kb + buf * 8192;
        const uint32_t Vt = Vb + buf * 8192;

        if (tt < 63) {
            const int n0 = (tt + 1) * 64;
            const uint32_t Kn = Kb + (buf ^ 1) * 8192;
            const uint32_t Vn = Vb + (buf ^ 1) * 8192;
            #pragma unroll
            for (int u = 0; u < 2; ++u) {
                int e = u * 256 + t, r = e >> 3, ch = e & 7;
                uint32_t off = SW((uint32_t)(r * 128 + ch * 16));
                cp16(Kn + off, &kp[((size_t)(b * N_ + n0 + r) << 3) + ch]);
                cp16(Vn + off, &vp[(((size_t)(b * C_ + r) * N_ + n0) >> 3) + ch]);
            }
        }
        CP_COMMIT();

        // ---- S = Q K^T (this warp's 32 keys: key-tiles 2nh, 2nh+1) ----
        float sc[2][4][4] = {};
        #pragma unroll
        for (int kk = 0; kk < 4; ++kk) {
            #pragma unroll
            for (int jp2 = 0; jp2 < 2; ++jp2) {
                uint32_t bk[4];
                ldsm4(bk, Kt + SW((uint32_t)((16 * (2 * nh + jp2) + prow) * 128 +
                                             (kk * 16 + pc8) * 2)));
                #pragma unroll
                for (int mt = 0; mt < 2; ++mt) {
                    mma16816(sc[mt][2 * jp2],     aq[mt][kk], bk);
                    mma16816(sc[mt][2 * jp2 + 1], aq[mt][kk], bk + 2);
                }
            }
        }

        // ---- softmax (non-centered, base 2) + pack P as A-fragments ----
        uint32_t pa[2][2][4];
        #pragma unroll
        for (int mt = 0; mt < 2; ++mt) {
            #pragma unroll
            for (int jo = 0; jo < 4; ++jo) {
                float e0 = ex2f(sc[mt][jo][0]);
                float e1 = ex2f(sc[mt][jo][1]);
                float e2 = ex2f(sc[mt][jo][2]);
                float e3 = ex2f(sc[mt][jo][3]);
                l0[mt] += e0 + e1;
                l1[mt] += e2 + e3;
                pa[mt][jo >> 1][(jo & 1) * 2 + 0] = pack_f16x2(e0, e1);
                pa[mt][jo >> 1][(jo & 1) * 2 + 1] = pack_f16x2(e2, e3);
            }
        }

        // ---- O += P V (k-dim = this warp's 32 keys; V cols nh*32+) ----
        #pragma unroll
        for (int kkp = 0; kkp < 2; ++kkp) {
            #pragma unroll
            for (int jp = 0; jp < 4; ++jp) {
                uint32_t bv[4];
                ldsm4(bv, Vt + SW((uint32_t)((16 * jp + prow) * 128 +
                                             (nh * 32 + kkp * 16 + pc8) * 2)));
                #pragma unroll
                for (int mt = 0; mt < 2; ++mt) {
                    mma16816(o[mt][2 * jp],     pa[mt][kkp], bv);
                    mma16816(o[mt][2 * jp + 1], pa[mt][kkp], bv + 2);
                }
            }
        }

        CP_WAIT0();
        __syncthreads();
    }

    // ---- quad-reduce l ----
    #pragma unroll
    for (int mt = 0; mt < 2; ++mt) {
        l0[mt] += __shfl_xor_sync(0xffffffffu, l0[mt], 1);
        l0[mt] += __shfl_xor_sync(0xffffffffu, l0[mt], 2);
        l1[mt] += __shfl_xor_sync(0xffffffffu, l1[mt], 1);
        l1[mt] += __shfl_xor_sync(0xffffffffu, l1[mt], 2);
    }

    const int g   = lane >> 2;
    const int tig = lane & 3;

    __syncthreads();   // K/V reads done -> safe to alias Ored over them

    // ---- cross-warp O/l reduction (key-half 1 -> smem) ----
    if (nh == 1) {
        #pragma unroll
        for (int mt = 0; mt < 2; ++mt) {
            const int r0 = 32 * mb + 16 * mt + g;
            const int r1 = r0 + 8;
            #pragma unroll
            for (int jj = 0; jj < 8; ++jj) {
                int ch = 8 * jj + 2 * tig;
                *(float2*)&Ored[r0 * 66 + ch] = make_float2(o[mt][jj][0], o[mt][jj][1]);
                *(float2*)&Ored[r1 * 66 + ch] = make_float2(o[mt][jj][2], o[mt][jj][3]);
            }
            if (tig == 0) {
                lred[r0] = l0[mt];
                lred[r1] = l1[mt];
            }
        }
    }
    __syncthreads();

    // ---- key-half 0 combines, normalizes, writes fp16 O tile (SW128) ----
    if (nh == 0) {
        #pragma unroll
        for (int mt = 0; mt < 2; ++mt) {
            const int r0 = 32 * mb + 16 * mt + g;
            const int r1 = r0 + 8;
            const float inv0 = 1.0f / (l0[mt] + lred[r0]);
            const float inv1 = 1.0f / (l1[mt] + lred[r1]);
            #pragma unroll
            for (int jj = 0; jj < 8; ++jj) {
                int ch = 8 * jj + 2 * tig;
                float2 p0 = *(float2*)&Ored[r0 * 66 + ch];
                float2 p1 = *(float2*)&Ored[r1 * 66 + ch];
                *(uint32_t*)(sm + SW((uint32_t)(r0 * 128 + ch * 2))) =
                    pack_f16x2((o[mt][jj][0] + p0.x) * inv0, (o[mt][jj][1] + p0.y) * inv0);
                *(uint32_t*)(sm + SW((uint32_t)(r1 * 128 + ch * 2))) =
                    pack_f16x2((o[mt][jj][2] + p1.x) * inv1, (o[mt][jj][3] + p1.y) * inv1);
            }
        }
    }
    __syncthreads();

    // ---- projection: out = O_norm * wp^T + bias + x ----
    const int m0 = 16 * w;   // back to 8-warp x 16-row split
    uint32_t oa[4][4];
    {
        const int a_r  = m0 + (lane & 7) + ((lane >> 3) & 1) * 8;
        const int a_c8 = ((lane >> 4) & 1) * 8;
        #pragma unroll
        for (int kk = 0; kk < 4; ++kk)
            ldsm4(oa[kk], Qb + SW((uint32_t)(a_r * 128 + (kk * 16 + a_c8) * 2)));
    }
    float po[8][4] = {};
    #pragma unroll
    for (int kk = 0; kk < 4; ++kk) {
        #pragma unroll
        for (int jp = 0; jp < 4; ++jp) {
            uint32_t bw[4];
            ldsm4(bw, Wb + SW((uint32_t)((16 * jp + prow) * 128 + (kk * 16 + pc8) * 2)));
            mma16816(po[2 * jp],     oa[kk], bw);
            mma16816(po[2 * jp + 1], oa[kk], bw + 2);
        }
    }

    const int n_a = q0 + m0 + g;
    const int n_b = n_a + 8;
    #pragma unroll
    for (int jj = 0; jj < 8; ++jj) {
        int och = 8 * jj + 2 * tig;
        float bb0 = bs[och], bb1 = bs[och + 1];
        size_t i00 = ((size_t)(b * C_ + och)) * N_ + n_a;
        size_t i10 = i00 + N_;              // och+1, n_a
        size_t i01 = i00 + 8;               // och,   n_b
        size_t i11 = i10 + 8;               // och+1, n_b
        out[i00] = po[jj][0] + bb0 + x[i00];
        out[i10] = po[jj][1] + bb1 + x[i10];
        out[i01] = po[jj][2] + bb0 + x[i01];
        out[i11] = po[jj][3] + bb1 + x[i11];
    }
}

// ---------------------------------------------------------------------------
extern "C" void kernel_launch(void* const* d_in, const int* in_sizes, int n_in,
                              void* d_out, int out_size)
{
    const float* x      = (const float*)d_in[0];
    const float* w_qkv  = (const float*)d_in[1];
    const float* b_qkv  = (const float*)d_in[2];
    const float* w_proj = (const float*)d_in[3];
    const float* b_proj = (const float*)d_in[4];
    float* out = (float*)d_out;

    cudaFuncSetAttribute(attn_proj_kernel,
                         cudaFuncAttributeMaxDynamicSharedMemorySize, SM_TOT);

    qkv_mma_kernel<<<dim3(N_ / 128, B_), 256>>>(x, w_qkv, b_qkv);
    attn_proj_kernel<<<dim3(N_ / 128, B_), 256, SM_TOT>>>(x, w_proj, b_proj, out);
}

// round 10
// speedup vs baseline: 16.0442x; 1.0348x over previous
#include <cuda_runtime.h>
#include <cuda_fp16.h>
#include <cstdint>

#define B_ 4
#define C_ 64
#define N_ 4096

// fp16 scratch
__device__ __half g_qh[B_ * N_ * C_]; // [b][n][c], pre-scaled by 0.125*log2e
__device__ __half g_kh[B_ * N_ * C_]; // [b][n][c]
__device__ __half g_vh[B_ * C_ * N_]; // [b][c][n]

// ---------------------------------------------------------------------------
// helpers (baseline PTX only — must compile for plain sm_103)
// ---------------------------------------------------------------------------
__device__ __forceinline__ uint32_t smem_u32(const void* p) {
    uint32_t a;
    asm("{ .reg .u64 t; cvta.to.shared.u64 t, %1; cvt.u32.u64 %0, t; }"
        : "=r"(a) : "l"(p));
    return a;
}
__device__ __forceinline__ float ex2f(float x) {
    float r; asm("ex2.approx.f32 %0, %1;" : "=f"(r) : "f"(x)); return r;
}
__device__ __forceinline__ uint32_t pack_f16x2(float lo, float hi) {
    uint32_t r;
    asm("cvt.rn.f16x2.f32 %0, %1, %2;" : "=r"(r) : "f"(hi), "f"(lo));
    return r;
}
__device__ __forceinline__ void ldsm4(uint32_t* r, uint32_t a) {
    asm volatile("ldmatrix.sync.aligned.m8n8.x4.shared.b16 {%0,%1,%2,%3}, [%4];"
                 : "=r"(r[0]), "=r"(r[1]), "=r"(r[2]), "=r"(r[3]) : "r"(a));
}
__device__ __forceinline__ void ldsm4t(uint32_t* r, uint32_t a) {
    asm volatile("ldmatrix.sync.aligned.m8n8.x4.trans.shared.b16 {%0,%1,%2,%3}, [%4];"
                 : "=r"(r[0]), "=r"(r[1]), "=r"(r[2]), "=r"(r[3]) : "r"(a));
}
__device__ __forceinline__ void mma16816(float* d, const uint32_t* a,
                                         const uint32_t* b) {
    asm volatile(
        "mma.sync.aligned.m16n8k16.row.col.f32.f16.f16.f32 "
        "{%0,%1,%2,%3}, {%4,%5,%6,%7}, {%8,%9}, {%0,%1,%2,%3};"
        : "+f"(d[0]), "+f"(d[1]), "+f"(d[2]), "+f"(d[3])
        : "r"(a[0]), "r"(a[1]), "r"(a[2]), "r"(a[3]), "r"(b[0]), "r"(b[1]));
}
__device__ __forceinline__ void cp16(uint32_t dst, const void* src) {
    asm volatile("cp.async.cg.shared.global [%0], [%1], 16;"
                 :: "r"(dst), "l"(src));
}
#define CP_COMMIT() asm volatile("cp.async.commit_group;" ::: "memory")
#define CP_WAIT0()  asm volatile("cp.async.wait_group 0;" ::: "memory")
#define SW(o) ((o) ^ (((o) >> 3) & 0x70))
#define QK_SCALE 0.18033688011112042f  // 0.125 * log2(e)

// ---------------------------------------------------------------------------
// QKV via HMMA (unchanged). grid (N/128, B), 256 thr.
// ---------------------------------------------------------------------------
__global__ __launch_bounds__(256) void qkv_mma_kernel(
    const float* __restrict__ x, const float* __restrict__ w,
    const float* __restrict__ bias)
{
    static __shared__ __align__(128) char smq[24576 + 16384 + 768];
    char* ws = smq;                     // [o 192][c 64] fp16, SW128 rows
    char* xs = smq + 24576;             // [c 64][n 128] fp16, 256B rows, chunk-XOR
    float* bs = (float*)(smq + 40960);  // bias[192]
    const uint32_t ws_b = smem_u32(ws);
    const uint32_t xs_b = smem_u32(xs);

    const int t    = threadIdx.x;
    const int wrp  = t >> 5;
    const int lane = t & 31;
    const int b    = blockIdx.y;
    const int n0   = blockIdx.x * 128;
    const int m0   = 16 * wrp;

    #pragma unroll
    for (int u = 0; u < 6; ++u) {
        int e = u * 256 + t, o = e >> 3, ch = e & 7;
        float4 w0 = *(const float4*)&w[o * 64 + ch * 8];
        float4 w1 = *(const float4*)&w[o * 64 + ch * 8 + 4];
        uint4 hv;
        hv.x = pack_f16x2(w0.x, w0.y);
        hv.y = pack_f16x2(w0.z, w0.w);
        hv.z = pack_f16x2(w1.x, w1.y);
        hv.w = pack_f16x2(w1.z, w1.w);
        *(uint4*)(ws + SW((uint32_t)(o * 128 + ch * 16))) = hv;
    }
    #pragma unroll
    for (int u = 0; u < 4; ++u) {
        int e = u * 256 + t, c = e >> 4, nch = e & 15;
        const float* xp = &x[((size_t)(b * C_ + c)) * N_ + n0 + nch * 8];
        float4 x0 = *(const float4*)xp;
        float4 x1 = *(const float4*)(xp + 4);
        uint4 hv;
        hv.x = pack_f16x2(x0.x, x0.y);
        hv.y = pack_f16x2(x0.z, x0.w);
        hv.z = pack_f16x2(x1.x, x1.y);
        hv.w = pack_f16x2(x1.z, x1.w);
        *(uint4*)(xs + (uint32_t)(c * 256 + ((nch ^ (c & 7)) << 4))) = hv;
    }
    if (t < 192) bs[t] = bias[t];
    __syncthreads();

    uint32_t aq[4][4];
    {
        const int c_l   = (lane & 7) + ((lane >> 4) & 1) * 8;
        const int chunk = ((m0 >> 3) + ((lane >> 3) & 1)) ^ (lane & 7);
        #pragma unroll
        for (int kk = 0; kk < 4; ++kk)
            ldsm4t(aq[kk], xs_b + (uint32_t)((kk * 16 + c_l) * 256 + chunk * 16));
    }

    float acc[24][4] = {};
    const int prow = (lane & 7) + ((lane >> 4) & 1) * 8;
    const int pc8  = ((lane >> 3) & 1) * 8;
    #pragma unroll
    for (int kk = 0; kk < 4; ++kk) {
        #pragma unroll
        for (int jp = 0; jp < 12; ++jp) {
            uint32_t bw[4];
            ldsm4(bw, ws_b + SW((uint32_t)((16 * jp + prow) * 128 + (kk * 16 + pc8) * 2)));
            mma16816(acc[2 * jp], aq[kk], bw);
            mma16816(acc[2 * jp + 1], aq[kk], bw + 2);
        }
    }

    const int g   = lane >> 2;
    const int tig = lane & 3;
    const int n_a = n0 + m0 + g;
    const int n_b = n_a + 8;
    #pragma unroll
    for (int j = 0; j < 8; ++j) {   // q (scaled)
        int o = 8 * j + 2 * tig;
        float b0 = bs[o], b1 = bs[o + 1];
        *(uint32_t*)&g_qh[((size_t)(b * N_ + n_a)) * C_ + o] =
            pack_f16x2((acc[j][0] + b0) * QK_SCALE, (acc[j][1] + b1) * QK_SCALE);
        *(uint32_t*)&g_qh[((size_t)(b * N_ + n_b)) * C_ + o] =
            pack_f16x2((acc[j][2] + b0) * QK_SCALE, (acc[j][3] + b1) * QK_SCALE);
    }
    #pragma unroll
    for (int j = 8; j < 16; ++j) {  // k
        int o = 8 * (j - 8) + 2 * tig;
        float b0 = bs[64 + o], b1 = bs[64 + o + 1];
        *(uint32_t*)&g_kh[((size_t)(b * N_ + n_a)) * C_ + o] =
            pack_f16x2(acc[j][0] + b0, acc[j][1] + b1);
        *(uint32_t*)&g_kh[((size_t)(b * N_ + n_b)) * C_ + o] =
            pack_f16x2(acc[j][2] + b0, acc[j][3] + b1);
    }
    __syncthreads();
    __half* vt = (__half*)smq;       // [o 64][n 128] pitch 136
    #pragma unroll
    for (int j = 16; j < 24; ++j) {  // v -> vt
        int o = 8 * (j - 16) + 2 * tig;
        float b0 = bs[128 + o], b1 = bs[128 + o + 1];
        int na = m0 + g, nb = na + 8;
        vt[o * 136 + na]       = __float2half(acc[j][0] + b0);
        vt[(o + 1) * 136 + na] = __float2half(acc[j][1] + b1);
        vt[o * 136 + nb]       = __float2half(acc[j][2] + b0);
        vt[(o + 1) * 136 + nb] = __float2half(acc[j][3] + b1);
    }
    __syncthreads();
    #pragma unroll
    for (int u = 0; u < 4; ++u) {
        int e = u * 256 + t, r = e >> 4, ch = e & 15;
        uint4 val = *(uint4*)&vt[r * 136 + ch * 8];
        *(uint4*)&g_vh[((size_t)(b * C_ + r)) * N_ + n0 + ch * 8] = val;
    }
}

// ---------------------------------------------------------------------------
// Fused flash attention + projection + residual.
// grid (N/64, B), 128 thr (4 warps) -> 2 CTAs/SM for issue overlap.
// Warp w: m-block mb=w&1 (32 of 64 q-rows), key-half nh=w>>1 (32 of 64 keys).
// SMEM map (bytes):
//   [0,8192)       Q tile fp16 SW128 (64 rows) -> reused as fp16 O tile
//   [8192,24576)   K double buf   (-> Ored fp32 64x66 aliases 8192.. after loop)
//   [24576,40960)  V double buf
//   [40960,49152)  wp fp16 SW128
//   [49152,49408)  lred fp32[64]
//   [49408,49664)  bias fp32[64]
// ---------------------------------------------------------------------------
#define SM_TOT (49664 + 128)

__global__ __launch_bounds__(128, 2) void attn_proj_kernel(
    const float* __restrict__ x, const float* __restrict__ wp,
    const float* __restrict__ bp, float* __restrict__ out)
{
    extern __shared__ char smraw[];
    char* sm = (char*)((((uintptr_t)smraw) + 127) & ~(uintptr_t)127);
    const uint32_t Qb = smem_u32(sm);
    const uint32_t Kb = Qb + 8192;
    const uint32_t Vb = Qb + 24576;
    const uint32_t Wb = Qb + 40960;
    float* Ored = (float*)(sm + 8192);    // pitch 66 floats, rows 64
    float* lred = (float*)(sm + 49152);
    float* bs   = (float*)(sm + 49408);

    const int t    = threadIdx.x;
    const int w    = t >> 5;
    const int lane = t & 31;
    const int b    = blockIdx.y;
    const int q0   = blockIdx.x * 64;
    const int mb   = w & 1;
    const int nh   = w >> 1;

    const uint4* qp = (const uint4*)g_qh;
    const uint4* kp = (const uint4*)g_kh;
    const uint4* vp = (const uint4*)g_vh;

    // Load Q tile (64 rows x 128B), SW128-swizzled
    #pragma unroll
    for (int u = 0; u < 4; ++u) {
        int e = u * 128 + t, r = e >> 3, ch = e & 7;
        uint32_t off = SW((uint32_t)(r * 128 + ch * 16));
        *(uint4*)(sm + off) = qp[((size_t)(b * N_ + q0 + r) << 3) + ch];
    }
    // Load wp (64x64 fp32 -> fp16 SW128 rows)
    #pragma unroll
    for (int u = 0; u < 4; ++u) {
        int e = u * 128 + t, o = e >> 3, ch = e & 7;
        float4 w0 = *(const float4*)&wp[o * 64 + ch * 8];
        float4 w1 = *(const float4*)&wp[o * 64 + ch * 8 + 4];
        uint4 hv;
        hv.x = pack_f16x2(w0.x, w0.y);
        hv.y = pack_f16x2(w0.z, w0.w);
        hv.z = pack_f16x2(w1.x, w1.y);
        hv.w = pack_f16x2(w1.z, w1.w);
        *(uint4*)(sm + (Wb - Qb) + SW((uint32_t)(o * 128 + ch * 16))) = hv;
    }
    if (t < 64) bs[t] = bp[t];
    // cp.async K/V tile 0 into buf 0
    #pragma unroll
    for (int u = 0; u < 4; ++u) {
        int e = u * 128 + t, r = e >> 3, ch = e & 7;
        uint32_t off = SW((uint32_t)(r * 128 + ch * 16));
        cp16(Kb + off, &kp[((size_t)(b * N_ + r) << 3) + ch]);
        cp16(Vb + off, &vp[(((size_t)(b * C_ + r) * N_) >> 3) + ch]);
    }
    CP_COMMIT();
    CP_WAIT0();
    __syncthreads();

    // Hoist Q A-fragments: 2 m16 tiles of this warp's 32 rows
    uint32_t aq[2][4][4];
    {
        const int a_c8 = ((lane >> 4) & 1) * 8;
        #pragma unroll
        for (int mt = 0; mt < 2; ++mt) {
            const int a_r = 32 * mb + 16 * mt + (lane & 7) + ((lane >> 3) & 1) * 8;
            #pragma unroll
            for (int kk = 0; kk < 4; ++kk)
                ldsm4(aq[mt][kk], Qb + SW((uint32_t)(a_r * 128 + (kk * 16 + a_c8) * 2)));
        }
    }

    const int prow = (lane & 7) + ((lane >> 4) & 1) * 8;
    const int pc8  = ((lane >> 3) & 1) * 8;

    float o[2][8][4] = {};
    float l0[2] = {0.f, 0.f}, l1[2] = {0.f, 0.f};

    for (int tt = 0; tt < 64; ++tt) {
        const int buf = tt & 1;
        const uint32_t Kt = Kb + buf * 8192;
        const uint32_t Vt = Vb + buf * 8192;

        if (tt < 63) {
            const int n0 = (tt + 1) * 64;
            const uint32_t Kn = Kb + (buf ^ 1) * 8192;
            const uint32_t Vn = Vb + (buf ^ 1) * 8192;
            #pragma unroll
            for (int u = 0; u < 4; ++u) {
                int e = u * 128 + t, r = e >> 3, ch = e & 7;
                uint32_t off = SW((uint32_t)(r * 128 + ch * 16));
                cp16(Kn + off, &kp[((size_t)(b * N_ + n0 + r) << 3) + ch]);
                cp16(Vn + off, &vp[(((size_t)(b * C_ + r) * N_ + n0) >> 3) + ch]);
            }
        }
        CP_COMMIT();

        // ---- S = Q K^T (this warp's 32 keys: key-tiles 2nh, 2nh+1) ----
        float sc[2][4][4] = {};
        #pragma unroll
        for (int kk = 0; kk < 4; ++kk) {
            #pragma unroll
            for (int jp2 = 0; jp2 < 2; ++jp2) {
                uint32_t bk[4];
                ldsm4(bk, Kt + SW((uint32_t)((16 * (2 * nh + jp2) + prow) * 128 +
                                             (kk * 16 + pc8) * 2)));
                #pragma unroll
                for (int mt = 0; mt < 2; ++mt) {
                    mma16816(sc[mt][2 * jp2],     aq[mt][kk], bk);
                    mma16816(sc[mt][2 * jp2 + 1], aq[mt][kk], bk + 2);
                }
            }
        }

        // ---- softmax (non-centered, base 2) + pack P as A-fragments ----
        uint32_t pa[2][2][4];
        #pragma unroll
        for (int mt = 0; mt < 2; ++mt) {
            #pragma unroll
            for (int jo = 0; jo < 4; ++jo) {
                float e0 = ex2f(sc[mt][jo][0]);
                float e1 = ex2f(sc[mt][jo][1]);
                float e2 = ex2f(sc[mt][jo][2]);
                float e3 = ex2f(sc[mt][jo][3]);
                l0[mt] += e0 + e1;
                l1[mt] += e2 + e3;
                pa[mt][jo >> 1][(jo & 1) * 2 + 0] = pack_f16x2(e0, e1);
                pa[mt][jo >> 1][(jo & 1) * 2 + 1] = pack_f16x2(e2, e3);
            }
        }

        // ---- O += P V (k-dim = this warp's 32 keys; V cols nh*32+) ----
        #pragma unroll
        for (int kkp = 0; kkp < 2; ++kkp) {
            #pragma unroll
            for (int jp = 0; jp < 4; ++jp) {
                uint32_t bv[4];
                ldsm4(bv, Vt + SW((uint32_t)((16 * jp + prow) * 128 +
                                             (nh * 32 + kkp * 16 + pc8) * 2)));
                #pragma unroll
                for (int mt = 0; mt < 2; ++mt) {
                    mma16816(o[mt][2 * jp],     pa[mt][kkp], bv);
                    mma16816(o[mt][2 * jp + 1], pa[mt][kkp], bv + 2);
                }
            }
        }

        CP_WAIT0();
        __syncthreads();
    }

    // ---- quad-reduce l ----
    #pragma unroll
    for (int mt = 0; mt < 2; ++mt) {
        l0[mt] += __shfl_xor_sync(0xffffffffu, l0[mt], 1);
        l0[mt] += __shfl_xor_sync(0xffffffffu, l0[mt], 2);
        l1[mt] += __shfl_xor_sync(0xffffffffu, l1[mt], 1);
        l1[mt] += __shfl_xor_sync(0xffffffffu, l1[mt], 2);
    }

    const int g   = lane >> 2;
    const int tig = lane & 3;

    __syncthreads();   // K/V reads done -> safe to alias Ored over K buffers

    // ---- cross-warp O/l reduction (key-half 1 -> smem) ----
    if (nh == 1) {
        #pragma unroll
        for (int mt = 0; mt < 2; ++mt) {
            const int r0 = 32 * mb + 16 * mt + g;
            const int r1 = r0 + 8;
            #pragma unroll
            for (int jj = 0; jj < 8; ++jj) {
                int ch = 8 * jj + 2 * tig;
                *(float2*)&Ored[r0 * 66 + ch] = make_float2(o[mt][jj][0], o[mt][jj][1]);
                *(float2*)&Ored[r1 * 66 + ch] = make_float2(o[mt][jj][2], o[mt][jj][3]);
            }
            if (tig == 0) {
                lred[r0] = l0[mt];
                lred[r1] = l1[mt];
            }
        }
    }
    __syncthreads();

    // ---- key-half 0 combines, normalizes, writes fp16 O tile (SW128) ----
    if (nh == 0) {
        #pragma unroll
        for (int mt = 0; mt < 2; ++mt) {
            const int r0 = 32 * mb + 16 * mt + g;
            const int r1 = r0 + 8;
            const float inv0 = 1.0f / (l0[mt] + lred[r0]);
            const float inv1 = 1.0f / (l1[mt] + lred[r1]);
            #pragma unroll
            for (int jj = 0; jj < 8; ++jj) {
                int ch = 8 * jj + 2 * tig;
                float2 p0 = *(float2*)&Ored[r0 * 66 + ch];
                float2 p1 = *(float2*)&Ored[r1 * 66 + ch];
                *(uint32_t*)(sm + SW((uint32_t)(r0 * 128 + ch * 2))) =
                    pack_f16x2((o[mt][jj][0] + p0.x) * inv0, (o[mt][jj][1] + p0.y) * inv0);
                *(uint32_t*)(sm + SW((uint32_t)(r1 * 128 + ch * 2))) =
                    pack_f16x2((o[mt][jj][2] + p1.x) * inv1, (o[mt][jj][3] + p1.y) * inv1);
            }
        }
    }
    __syncthreads();

    // ---- projection: out = O_norm * wp^T + bias + x ----
    const int m0 = 16 * w;   // 4-warp x 16-row split of the 64-row tile
    uint32_t oa[4][4];
    {
        const int a_r  = m0 + (lane & 7) + ((lane >> 3) & 1) * 8;
        const int a_c8 = ((lane >> 4) & 1) * 8;
        #pragma unroll
        for (int kk = 0; kk < 4; ++kk)
            ldsm4(oa[kk], Qb + SW((uint32_t)(a_r * 128 + (kk * 16 + a_c8) * 2)));
    }
    float po[8][4] = {};
    #pragma unroll
    for (int kk = 0; kk < 4; ++kk) {
        #pragma unroll
        for (int jp = 0; jp < 4; ++jp) {
            uint32_t bw[4];
            ldsm4(bw, Wb + SW((uint32_t)((16 * jp + prow) * 128 + (kk * 16 + pc8) * 2)));
            mma16816(po[2 * jp],     oa[kk], bw);
            mma16816(po[2 * jp + 1], oa[kk], bw + 2);
        }
    }

    const int n_a = q0 + m0 + g;
    const int n_b = n_a + 8;
    #pragma unroll
    for (int jj = 0; jj < 8; ++jj) {
        int och = 8 * jj + 2 * tig;
        float bb0 = bs[och], bb1 = bs[och + 1];
        size_t i00 = ((size_t)(b * C_ + och)) * N_ + n_a;
        size_t i10 = i00 + N_;              // och+1, n_a
        size_t i01 = i00 + 8;               // och,   n_b
        size_t i11 = i10 + 8;               // och+1, n_b
        out[i00] = po[jj][0] + bb0 + x[i00];
        out[i10] = po[jj][1] + bb1 + x[i10];
        out[i01] = po[jj][2] + bb0 + x[i01];
        out[i11] = po[jj][3] + bb1 + x[i11];
    }
}

// ---------------------------------------------------------------------------
extern "C" void kernel_launch(void* const* d_in, const int* in_sizes, int n_in,
                              void* d_out, int out_size)
{
    const float* x      = (const float*)d_in[0];
    const float* w_qkv  = (const float*)d_in[1];
    const float* b_qkv  = (const float*)d_in[2];
    const float* w_proj = (const float*)d_in[3];
    const float* b_proj = (const float*)d_in[4];
    float* out = (float*)d_out;

    cudaFuncSetAttribute(attn_proj_kernel,
                         cudaFuncAttributeMaxDynamicSharedMemorySize, SM_TOT);

    qkv_mma_kernel<<<dim3(N_ / 128, B_), 256>>>(x, w_qkv, b_qkv);
    attn_proj_kernel<<<dim3(N_ / 64, B_), 128, SM_TOT>>>(x, w_proj, b_proj, out);
}